// round 2
// baseline (speedup 1.0000x reference)
#include <cuda_runtime.h>

#define EMB   512
#define BATCH 256
#define G3    1536
#define NCLS  6
#define NCTA  128
#define NTHR  256
#define TMAX  512
#define CONV_EPS 1e-5f

typedef unsigned long long ull;

// ---- persistent device state (allocation-free scratch) ----
__device__ float g_x[BATCH * EMB];
__device__ float g_gi[BATCH * G3];
__device__ float g_h[2][BATCH * EMB];
__device__ int   g_md[TMAX];
__device__ unsigned g_count;
__device__ volatile unsigned g_gen;

// ---- packed f32x2 helpers (sm_100+) ----
__device__ __forceinline__ ull pk2(float lo, float hi) {
    ull r; asm("mov.b64 %0, {%1, %2};" : "=l"(r) : "f"(lo), "f"(hi)); return r;
}
__device__ __forceinline__ void fma2(ull &a, ull x, ull y) {
    asm("fma.rn.f32x2 %0, %1, %2, %0;" : "+l"(a) : "l"(x), "l"(y));
}
__device__ __forceinline__ float2 unpk(ull a) {
    float2 v; asm("mov.b64 {%0, %1}, %2;" : "=f"(v.x), "=f"(v.y) : "l"(a)); return v;
}
__device__ __forceinline__ float sigm(float v) { return 1.f / (1.f + __expf(-v)); }

// ---- grid-wide sense-reversing barrier (all NCTA CTAs co-resident) ----
__device__ __forceinline__ void gridbar() {
    __syncthreads();
    __threadfence();
    if (threadIdx.x == 0) {
        unsigned my = g_gen;
        unsigned a = atomicAdd(&g_count, 1u);
        if (a == NCTA - 1u) {
            g_count = 0;
            __threadfence();
            g_gen = my + 1u;
        } else {
            while (g_gen == my) { }
        }
    }
    __syncthreads();
    __threadfence();
}

__global__ void __launch_bounds__(NTHR, 1)
gru_persistent_kernel(const float* __restrict__ c,     const float* __restrict__ fc_w,
                      const float* __restrict__ fc_b,  const float* __restrict__ w_ih,
                      const float* __restrict__ b_ih,  const float* __restrict__ w_hh,
                      const float* __restrict__ b_hh,  const float* __restrict__ head_w,
                      const float* __restrict__ head_b,const int*   __restrict__ maxT,
                      float* __restrict__ out)
{
    const int tid = threadIdx.x;
    const int cta = blockIdx.x;
    const int gt  = cta * NTHR + tid;

    int T = (maxT != nullptr) ? maxT[0] : TMAX;
    if (T < 1 || T > TMAX) T = TMAX;

    // ---------------- Phase A: zero state, compute x = tanh(c @ fc_w^T + fc_b) ----
    for (int i = gt; i < BATCH * EMB; i += NCTA * NTHR) __stcg(&g_h[0][i], 0.f);
    for (int i = gt; i < TMAX; i += NCTA * NTHR) ((volatile int*)g_md)[i] = 0;

    for (int o = gt; o < BATCH * EMB; o += NCTA * NTHR) {
        int b = o >> 9, i = o & (EMB - 1);
        const float4* cr = (const float4*)(c + (size_t)b * EMB);
        const float4* wr = (const float4*)(fc_w + (size_t)i * EMB);
        float s = 0.f;
        #pragma unroll 8
        for (int k = 0; k < EMB / 4; k++) {
            float4 a = cr[k], w = wr[k];
            s += a.x * w.x + a.y * w.y + a.z * w.z + a.w * w.w;
        }
        g_x[o] = tanhf(s + fc_b[i]);
    }
    gridbar();

    // ---------------- Phase B: gi = x @ w_ih^T + b_ih (constant over time) --------
    for (int o = gt; o < BATCH * G3; o += NCTA * NTHR) {
        int b = o / G3, m = o % G3;
        const float4* xr = (const float4*)(g_x + (size_t)b * EMB);
        const float4* wr = (const float4*)(w_ih + (size_t)m * EMB);
        float s = 0.f;
        #pragma unroll 8
        for (int k = 0; k < EMB / 4; k++) {
            float4 a = xr[k], w = wr[k];
            s += a.x * w.x + a.y * w.y + a.z * w.z + a.w * w.w;
        }
        g_gi[o] = s + b_ih[m];
    }
    gridbar();

    // ---------------- Recurrent loop ------------------------------------------
    __shared__ float hs[64][68];      // hs[k][b], transposed for contiguous b-pairs
    __shared__ float ws[3][64][17];   // ws[gate][k][j]
    __shared__ int   s_mx;

    const int tx = tid & 15, ty = tid >> 4;
    const int btile = cta >> 5, jtile = cta & 31;
    const int B0 = btile * 64, J0 = jtile * 16;
    const int j   = J0 + tx;
    const int ty4 = ty * 4;

    // step-invariant per-thread constants (L1-resident)
    const float bhr = b_hh[j], bhz = b_hh[EMB + j], bhn = b_hh[2 * EMB + j];
    float gir[4], giz[4], gin[4];
    #pragma unroll
    for (int i = 0; i < 4; i++) {
        int b = B0 + ty4 + i;
        gir[i] = g_gi[(size_t)b * G3 + j];
        giz[i] = g_gi[(size_t)b * G3 + EMB + j];
        gin[i] = g_gi[(size_t)b * G3 + 2 * EMB + j];
    }

    const int group = tid >> 4;        // head-projection work groups (12 used)
    const int lane  = tid & 15;

    for (int t = 0; t < T; t++) {
        const float* hcur = g_h[t & 1];
        float*       hnxt = g_h[(t & 1) ^ 1];

        if (tid == 0) s_mx = 0;

        ull a0r = 0, a0z = 0, a0n = 0, a1r = 0, a1z = 0, a1n = 0;

        for (int kc = 0; kc < EMB; kc += 64) {
            // stage h chunk (transposed) — L2 via ldcg (cross-CTA coherence)
            #pragma unroll
            for (int e = tid; e < 1024; e += NTHR) {
                int b = e >> 4, k4 = (e & 15) << 2;
                float4 v = __ldcg((const float4*)&hcur[(size_t)(B0 + b) * EMB + kc + k4]);
                hs[k4 + 0][b] = v.x; hs[k4 + 1][b] = v.y;
                hs[k4 + 2][b] = v.z; hs[k4 + 3][b] = v.w;
            }
            // stage w_hh chunk (plain loads -> stays hot in L1 across steps)
            #pragma unroll
            for (int e = tid; e < 768; e += NTHR) {
                int g = e >> 8, r = e & 255, jj = r >> 4, k4 = (r & 15) << 2;
                float4 v = *(const float4*)&w_hh[(size_t)(g * EMB + J0 + jj) * EMB + kc + k4];
                ws[g][k4 + 0][jj] = v.x; ws[g][k4 + 1][jj] = v.y;
                ws[g][k4 + 2][jj] = v.z; ws[g][k4 + 3][jj] = v.w;
            }
            __syncthreads();

            #pragma unroll 16
            for (int k = 0; k < 64; k++) {
                ull h01 = *(const ull*)&hs[k][ty4];
                ull h23 = *(const ull*)&hs[k][ty4 + 2];
                float w0 = ws[0][k][tx], w1 = ws[1][k][tx], w2 = ws[2][k][tx];
                ull wr2 = pk2(w0, w0), wz2 = pk2(w1, w1), wn2 = pk2(w2, w2);
                fma2(a0r, h01, wr2); fma2(a1r, h23, wr2);
                fma2(a0z, h01, wz2); fma2(a1z, h23, wz2);
                fma2(a0n, h01, wn2); fma2(a1n, h23, wn2);
            }
            __syncthreads();
        }

        // gates + h update for this thread's 4 (b, j) cells
        float2 vr0 = unpk(a0r), vr1 = unpk(a1r);
        float2 vz0 = unpk(a0z), vz1 = unpk(a1z);
        float2 vn0 = unpk(a0n), vn1 = unpk(a1n);
        float accr[4] = { vr0.x, vr0.y, vr1.x, vr1.y };
        float accz[4] = { vz0.x, vz0.y, vz1.x, vz1.y };
        float accn[4] = { vn0.x, vn0.y, vn1.x, vn1.y };

        float mx = 0.f;
        #pragma unroll
        for (int i = 0; i < 4; i++) {
            int b = B0 + ty4 + i;
            float r = sigm(gir[i] + accr[i] + bhr);
            float z = sigm(giz[i] + accz[i] + bhz);
            float n = tanhf(gin[i] + (accn[i] + bhn) * r);
            float hold = __ldcg(&hcur[(size_t)b * EMB + j]);
            float hnew = (1.f - z) * n + z * hold;
            __stcg(&hnxt[(size_t)b * EMB + j], hnew);
            mx = fmaxf(mx, fabsf(hnew - hold));
        }
        atomicMax(&s_mx, __float_as_int(mx));
        __syncthreads();
        if (tid == 0) atomicMax(&g_md[t], s_mx);

        gridbar();   // h_{t+1} fully visible; g_md[t] final

        bool conv = (__int_as_float(((volatile int*)g_md)[t]) < CONV_EPS);

        // head: out[:, t, :] = h_{t+1} @ head_w^T + head_b. 1536 dots / 128 CTAs = 12.
        if (group < 12) {
            int p = cta * 12 + group;
            int b = p / NCLS, k = p % NCLS;
            const float* hr = hnxt + (size_t)b * EMB;
            const float* wr = head_w + (size_t)k * EMB;
            float s = 0.f;
            #pragma unroll 8
            for (int jj = lane; jj < EMB; jj += 16) s += __ldcg(&hr[jj]) * wr[jj];
            unsigned m = 0xFFFFu << (tid & 16);
            s += __shfl_down_sync(m, s, 8, 16);
            s += __shfl_down_sync(m, s, 4, 16);
            s += __shfl_down_sync(m, s, 2, 16);
            s += __shfl_down_sync(m, s, 1, 16);
            if (lane == 0) {
                float val = s + head_b[k];
                size_t base = (size_t)b * T * NCLS + (size_t)k;
                out[base + (size_t)t * NCLS] = val;
                if (conv) {
                    // fixed point reached: all remaining outputs are identical
                    for (int tt = t + 1; tt < T; tt++)
                        out[base + (size_t)tt * NCLS] = val;
                }
            }
        }
        if (conv) break;
    }
}

extern "C" void kernel_launch(void* const* d_in, const int* in_sizes, int n_in,
                              void* d_out, int out_size)
{
    (void)in_sizes; (void)out_size;
    const float* c      = (const float*)d_in[0];
    const float* fc_w   = (const float*)d_in[1];
    const float* fc_b   = (const float*)d_in[2];
    const float* w_ih   = (const float*)d_in[3];
    const float* b_ih   = (const float*)d_in[4];
    const float* w_hh   = (const float*)d_in[5];
    const float* b_hh   = (const float*)d_in[6];
    const float* head_w = (const float*)d_in[7];
    const float* head_b = (const float*)d_in[8];
    const int*   maxT   = (n_in > 9) ? (const int*)d_in[9] : nullptr;

    gru_persistent_kernel<<<NCTA, NTHR>>>(c, fc_w, fc_b, w_ih, b_ih, w_hh, b_hh,
                                          head_w, head_b, maxT, (float*)d_out);
}

// round 3
// speedup vs baseline: 2.5671x; 2.5671x over previous
#include <cuda_runtime.h>

#define EMB   512
#define BATCH 256
#define NCLS  6
#define NCTA  128
#define NTHR  256
#define TMAX  512
#define CONV_EPS 2e-4f

#define HS_PITCH 66
#define KCHUNK   128
#define NCHUNK   4
#define RED_PITCH 50

#define HS_BUF  (KCHUNK * HS_PITCH)              // 8448 floats per buffer
#define WS_OFF  0                                // 3*512*16 = 24576 floats
#define HS_OFF  24576
#define RED_OFF (HS_OFF + 2 * HS_BUF)            // 41472
#define SMX_OFF (RED_OFF + 4 * 64 * RED_PITCH)   // 54272
#define SMEM_FLOATS (SMX_OFF + 4)
#define SMEM_BYTES  (SMEM_FLOATS * 4)            // ~217 KB

typedef unsigned long long ull;

// ---- persistent device state ----
__device__ float g_x[BATCH * EMB];
__device__ float g_h[2][BATCH * EMB];
__device__ int   g_md[TMAX];
__device__ unsigned g_count;
__device__ volatile unsigned g_gen;

// ---- packed f32x2 helpers ----
__device__ __forceinline__ ull pk2(float lo, float hi) {
    ull r; asm("mov.b64 %0, {%1, %2};" : "=l"(r) : "f"(lo), "f"(hi)); return r;
}
__device__ __forceinline__ void fma2(ull &a, ull x, ull y) {
    asm("fma.rn.f32x2 %0, %1, %2, %0;" : "+l"(a) : "l"(x), "l"(y));
}
__device__ __forceinline__ float sigm(float v) { return 1.f / (1.f + __expf(-v)); }

// ---- grid-wide sense-reversing barrier ----
__device__ __forceinline__ void gridbar() {
    __syncthreads();
    __threadfence();
    if (threadIdx.x == 0) {
        unsigned my = g_gen;
        unsigned a = atomicAdd(&g_count, 1u);
        if (a == NCTA - 1u) {
            g_count = 0;
            __threadfence();
            g_gen = my + 1u;
        } else {
            while (g_gen == my) { }
        }
    }
    __syncthreads();
    __threadfence();
}

// ---- staging: global h/x rows -> transposed smem chunk hs[k][b] (pitch 66) ----
__device__ __forceinline__ void stage_load(float4 v[8], const float* src, int B0, int kc,
                                           int wid, int lane) {
    const float* s = src + (size_t)B0 * EMB + kc;
    #pragma unroll
    for (int r = 0; r < 8; r++) {
        int k4 = ((lane & 7) + ((r & 3) << 3)) << 2;          // 0..124
        int b  = (lane >> 3) + ((r >> 2) & 1) * 4 + wid * 8;  // 0..63
        v[r] = __ldcg((const float4*)(s + (size_t)b * EMB + k4));
    }
}
__device__ __forceinline__ void stage_store(float* hsbuf, const float4 v[8], int wid, int lane) {
    #pragma unroll
    for (int r = 0; r < 8; r++) {
        int k4 = ((lane & 7) + ((r & 3) << 3)) << 2;
        int b  = (lane >> 3) + ((r >> 2) & 1) * 4 + wid * 8;
        hsbuf[(k4 + 0) * HS_PITCH + b] = v[r].x;
        hsbuf[(k4 + 1) * HS_PITCH + b] = v[r].y;
        hsbuf[(k4 + 2) * HS_PITCH + b] = v[r].z;
        hsbuf[(k4 + 3) * HS_PITCH + b] = v[r].w;
    }
}

// ---- compute one 128-k chunk (this thread covers its kg's 32 k's) ----
__device__ __forceinline__ void compute_chunk(ull acc[3][2][4], const float* hsbuf,
                                              const float* wchunk, int kg, int bg, int jp) {
    const float* hrow = hsbuf + kg * 32 * HS_PITCH + bg * 8;
    const float* wrow = wchunk + (kg * 32) * 16 + jp * 2;
    #pragma unroll 8
    for (int i = 0; i < 32; i++) {
        ull h0 = *(const ull*)(hrow + i * HS_PITCH + 0);
        ull h1 = *(const ull*)(hrow + i * HS_PITCH + 2);
        ull h2 = *(const ull*)(hrow + i * HS_PITCH + 4);
        ull h3 = *(const ull*)(hrow + i * HS_PITCH + 6);
        #pragma unroll
        for (int g = 0; g < 3; g++) {
            float2 wv = *(const float2*)(wrow + g * (EMB * 16) + i * 16);
            ull w0 = pk2(wv.x, wv.x), w1 = pk2(wv.y, wv.y);
            fma2(acc[g][0][0], h0, w0); fma2(acc[g][0][1], h1, w0);
            fma2(acc[g][0][2], h2, w0); fma2(acc[g][0][3], h3, w0);
            fma2(acc[g][1][0], h0, w1); fma2(acc[g][1][1], h1, w1);
            fma2(acc[g][1][2], h2, w1); fma2(acc[g][1][3], h3, w1);
        }
    }
}

// ---- full K=512 pass: acc += src[64b x 512k] @ ws (double-buffered chunks) ----
__device__ __forceinline__ void mm_pass(ull acc[3][2][4], const float* src, float* hs,
                                        const float* ws, int B0,
                                        int kg, int bg, int jp, int wid, int lane) {
    float4 v[8];
    stage_load(v, src, B0, 0, wid, lane);
    stage_store(hs, v, wid, lane);
    __syncthreads();
    for (int c = 0; c < NCHUNK; c++) {
        if (c + 1 < NCHUNK) stage_load(v, src, B0, (c + 1) * KCHUNK, wid, lane);
        compute_chunk(acc, hs + (c & 1) * HS_BUF, ws + c * KCHUNK * 16, kg, bg, jp);
        if (c + 1 < NCHUNK) stage_store(hs + ((c + 1) & 1) * HS_BUF, v, wid, lane);
        __syncthreads();
    }
}

// ---- load a [3E, E] weight slice (16 j's) into smem ws[g][k][jj] ----
__device__ __forceinline__ void load_ws(float* ws, const float* wsrc, int J0, int tid) {
    #pragma unroll
    for (int e = tid; e < 6144; e += NTHR) {
        int jj = e & 15, k4 = ((e >> 4) & 127) << 2, g = e >> 11;
        float4 v = *(const float4*)(wsrc + ((size_t)(g * EMB + J0 + jj)) * EMB + k4);
        ws[(g * EMB + k4 + 0) * 16 + jj] = v.x;
        ws[(g * EMB + k4 + 1) * 16 + jj] = v.y;
        ws[(g * EMB + k4 + 2) * 16 + jj] = v.z;
        ws[(g * EMB + k4 + 3) * 16 + jj] = v.w;
    }
}

__global__ void __launch_bounds__(NTHR, 1)
gru_persistent_kernel(const float* __restrict__ c,     const float* __restrict__ fc_w,
                      const float* __restrict__ fc_b,  const float* __restrict__ w_ih,
                      const float* __restrict__ b_ih,  const float* __restrict__ w_hh,
                      const float* __restrict__ b_hh,  const float* __restrict__ head_w,
                      const float* __restrict__ head_b,const int*   __restrict__ maxT,
                      float* __restrict__ out)
{
    extern __shared__ float sm[];
    float* ws  = sm + WS_OFF;
    float* hs  = sm + HS_OFF;
    float* red = sm + RED_OFF;
    int*   s_mx = (int*)(sm + SMX_OFF);

    const int tid = threadIdx.x;
    const int cta = blockIdx.x;
    const int gt  = cta * NTHR + tid;

    int T = (maxT != nullptr) ? maxT[0] : TMAX;
    if (T < 1 || T > TMAX) T = TMAX;

    const int btile = cta >> 5, jtile = cta & 31;
    const int B0 = btile * 64, J0 = jtile * 16;
    const int kg = tid >> 6, w = tid & 63, bg = w >> 3, jp = w & 7;
    const int wid = tid >> 5, lane = tid & 31;
    const int group = tid >> 4, lane16 = tid & 15;

    // ---------------- Phase A: init + x = tanh(c @ fc_w^T + fc_b) ----------------
    for (int i = gt; i < BATCH * EMB; i += NCTA * NTHR) __stcg(&g_h[0][i], 0.f);
    for (int i = gt; i < TMAX; i += NCTA * NTHR) ((volatile int*)g_md)[i] = 0;

    for (int o = gt; o < BATCH * EMB; o += NCTA * NTHR) {
        int b = o >> 9, i = o & (EMB - 1);
        const float4* cr = (const float4*)(c + (size_t)b * EMB);
        const float4* wr = (const float4*)(fc_w + (size_t)i * EMB);
        float s = 0.f;
        #pragma unroll 8
        for (int k = 0; k < EMB / 4; k++) {
            float4 a = cr[k], wv = wr[k];
            s += a.x * wv.x + a.y * wv.y + a.z * wv.z + a.w * wv.w;
        }
        __stcg(&g_x[o], tanhf(s + fc_b[i]));
    }
    gridbar();

    // ---------------- gi pass: ws <- w_ih ; gi = x @ w_ih^T (kept in registers) --
    load_ws(ws, w_ih, J0, tid);
    __syncthreads();

    ull acc[3][2][4];
    #pragma unroll
    for (int g = 0; g < 3; g++)
        #pragma unroll
        for (int jl = 0; jl < 2; jl++)
            #pragma unroll
            for (int bp = 0; bp < 4; bp++) acc[g][jl][bp] = 0ull;

    mm_pass(acc, g_x, hs, ws, B0, kg, bg, jp, wid, lane);

    {   // store partials
        ull* rp = (ull*)(red + (size_t)(kg * 64 + w) * RED_PITCH);
        #pragma unroll
        for (int g = 0; g < 3; g++)
            #pragma unroll
            for (int jl = 0; jl < 2; jl++)
                #pragma unroll
                for (int bp = 0; bp < 4; bp++)
                    rp[g * 8 + jl * 4 + bp] = acc[g][jl][bp];
    }
    __syncthreads();

    // per-thread step-invariant gate constants (gi + biases folded)
    float gir[4], giz[4], gin[4], bhn[4];
    int   hoff[4], rb[4];
    #pragma unroll
    for (int q = 0; q < 4; q++) {
        int pid = (tid << 2) + q;
        int b = pid >> 4, jj = pid & 15;
        int jl = jj & 1, wq = (b >> 3) * 8 + (jj >> 1);
        int bi = b & 7, bp = bi >> 1, hf = bi & 1;
        rb[q] = wq * RED_PITCH + jl * 8 + bp * 2 + hf;
        float sr = 0.f, sz = 0.f, sn = 0.f;
        #pragma unroll
        for (int kgi = 0; kgi < 4; kgi++) {
            const float* rp = red + kgi * 64 * RED_PITCH + rb[q];
            sr += rp[0]; sz += rp[16]; sn += rp[32];
        }
        int jg = J0 + jj, bgl = B0 + b;
        gir[q] = sr + b_ih[jg] + b_hh[jg];
        giz[q] = sz + b_ih[EMB + jg] + b_hh[EMB + jg];
        gin[q] = sn + b_ih[2 * EMB + jg];
        bhn[q] = b_hh[2 * EMB + jg];
        hoff[q] = bgl * EMB + jg;
    }
    __syncthreads();

    // ---------------- ws <- w_hh (persistent for the whole recurrence) -----------
    load_ws(ws, w_hh, J0, tid);
    __syncthreads();

    // ---------------- Recurrent loop ---------------------------------------------
    for (int t = 0; t < T; t++) {
        const float* hcur = g_h[t & 1];
        float*       hnxt = g_h[(t & 1) ^ 1];

        if (tid == 0) *s_mx = 0;

        #pragma unroll
        for (int g = 0; g < 3; g++)
            #pragma unroll
            for (int jl = 0; jl < 2; jl++)
                #pragma unroll
                for (int bp = 0; bp < 4; bp++) acc[g][jl][bp] = 0ull;

        mm_pass(acc, hcur, hs, ws, B0, kg, bg, jp, wid, lane);

        {
            ull* rp = (ull*)(red + (size_t)(kg * 64 + w) * RED_PITCH);
            #pragma unroll
            for (int g = 0; g < 3; g++)
                #pragma unroll
                for (int jl = 0; jl < 2; jl++)
                    #pragma unroll
                    for (int bp = 0; bp < 4; bp++)
                        rp[g * 8 + jl * 4 + bp] = acc[g][jl][bp];
        }
        __syncthreads();

        float mx = 0.f;
        #pragma unroll
        for (int q = 0; q < 4; q++) {
            float sr = 0.f, sz = 0.f, sn = 0.f;
            #pragma unroll
            for (int kgi = 0; kgi < 4; kgi++) {
                const float* rp = red + kgi * 64 * RED_PITCH + rb[q];
                sr += rp[0]; sz += rp[16]; sn += rp[32];
            }
            float r = sigm(gir[q] + sr);
            float z = sigm(giz[q] + sz);
            float n = tanhf(gin[q] + r * (sn + bhn[q]));
            float hold = __ldcg(hcur + hoff[q]);
            float hnew = (1.f - z) * n + z * hold;
            __stcg(hnxt + hoff[q], hnew);
            mx = fmaxf(mx, fabsf(hnew - hold));
        }
        atomicMax(s_mx, __float_as_int(mx));
        __syncthreads();
        if (tid == 0) atomicMax(&g_md[t], *s_mx);

        gridbar();   // h_{t+1} and g_md[t] globally visible

        bool conv = (__int_as_float(((volatile int*)g_md)[t]) < CONV_EPS);

        // head: out[:, t, :] = h_{t+1} @ head_w^T + head_b (1536 dots / 128 CTAs)
        if (group < 12) {
            int p = cta * 12 + group;
            int b = p / NCLS, k = p % NCLS;
            const float* hr = hnxt + (size_t)b * EMB;
            const float* wr = head_w + (size_t)k * EMB;
            float s = 0.f;
            #pragma unroll 8
            for (int jj = lane16; jj < EMB; jj += 16) s += __ldcg(&hr[jj]) * wr[jj];
            unsigned m = 0xFFFFu << (tid & 16);
            s += __shfl_down_sync(m, s, 8, 16);
            s += __shfl_down_sync(m, s, 4, 16);
            s += __shfl_down_sync(m, s, 2, 16);
            s += __shfl_down_sync(m, s, 1, 16);
            if (lane16 == 0) {
                float val = s + head_b[k];
                size_t base = (size_t)b * T * NCLS + (size_t)k;
                out[base + (size_t)t * NCLS] = val;
                if (conv) {
                    for (int tt = t + 1; tt < T; tt++)
                        out[base + (size_t)tt * NCLS] = val;
                }
            }
        }
        if (conv) break;
    }
}

extern "C" void kernel_launch(void* const* d_in, const int* in_sizes, int n_in,
                              void* d_out, int out_size)
{
    (void)in_sizes; (void)out_size;
    const float* c      = (const float*)d_in[0];
    const float* fc_w   = (const float*)d_in[1];
    const float* fc_b   = (const float*)d_in[2];
    const float* w_ih   = (const float*)d_in[3];
    const float* b_ih   = (const float*)d_in[4];
    const float* w_hh   = (const float*)d_in[5];
    const float* b_hh   = (const float*)d_in[6];
    const float* head_w = (const float*)d_in[7];
    const float* head_b = (const float*)d_in[8];
    const int*   maxT   = (n_in > 9) ? (const int*)d_in[9] : nullptr;

    cudaFuncSetAttribute(gru_persistent_kernel,
                         cudaFuncAttributeMaxDynamicSharedMemorySize, SMEM_BYTES);
    gru_persistent_kernel<<<NCTA, NTHR, SMEM_BYTES>>>(c, fc_w, fc_b, w_ih, b_ih,
                                                      w_hh, b_hh, head_w, head_b,
                                                      maxT, (float*)d_out);
}

// round 5
// speedup vs baseline: 4.2059x; 1.6384x over previous
#include <cuda_runtime.h>
#include <cuda_bf16.h>

#define EMB   512
#define BATCH 256
#define NCLS  6
#define NCTA  128
#define NTHR  256
#define TMAX  512
#define CONV_EPS 6e-4f

#define APITCH 272    // bytes/row of h chunk in smem (136 bf16): 68 mod 32 = 4-bank rotation
#define BPITCH 1040   // bytes/row of w in smem (520 bf16): 260 mod 32 = 4-bank rotation
#define WS_PL  49920  // one w plane: 48 * 1040
#define HS_OFF 99840
#define HS_PL  17408  // one h plane chunk: 64 * 272
#define HS_BUF 34816  // 2 planes
#define SMX_OFF 169472
#define SMEM_BYTES 169600

typedef unsigned int u32;
typedef unsigned long long u64;
typedef unsigned short us16;

// ---- persistent device state ----
__device__ us16 g_xp[2][BATCH * EMB];        // x bf16 hi/lo planes
__device__ us16 g_hp[2][2][BATCH * EMB];     // h[step parity][plane]
__device__ int  g_md[TMAX];
__device__ unsigned g_count;
__device__ volatile unsigned g_gen;

__device__ __forceinline__ u32 smem_u32(const void* p) {
    u32 a; asm("{ .reg .u64 t; cvta.to.shared.u64 t, %1; cvt.u32.u64 %0, t; }" : "=r"(a) : "l"(p));
    return a;
}
__device__ __forceinline__ void cp16(u32 dst, const void* src) {
    u64 g = (u64)__cvta_generic_to_global(src);
    asm volatile("cp.async.cg.shared.global [%0], [%1], 16;" :: "r"(dst), "l"(g));
}
__device__ __forceinline__ void ldsm_x4(u32& r0, u32& r1, u32& r2, u32& r3, u32 addr) {
    asm volatile("ldmatrix.sync.aligned.m8n8.x4.shared.b16 {%0,%1,%2,%3}, [%4];"
                 : "=r"(r0), "=r"(r1), "=r"(r2), "=r"(r3) : "r"(addr));
}
__device__ __forceinline__ void ldsm_x2(u32& r0, u32& r1, u32 addr) {
    asm volatile("ldmatrix.sync.aligned.m8n8.x2.shared.b16 {%0,%1}, [%2];"
                 : "=r"(r0), "=r"(r1) : "r"(addr));
}
__device__ __forceinline__ void mma16816(float* d, u32 a0, u32 a1, u32 a2, u32 a3,
                                         u32 b0, u32 b1) {
    asm volatile("mma.sync.aligned.m16n8k16.row.col.f32.bf16.bf16.f32 "
                 "{%0,%1,%2,%3}, {%4,%5,%6,%7}, {%8,%9}, {%0,%1,%2,%3};"
                 : "+f"(d[0]), "+f"(d[1]), "+f"(d[2]), "+f"(d[3])
                 : "r"(a0), "r"(a1), "r"(a2), "r"(a3), "r"(b0), "r"(b1));
}
__device__ __forceinline__ float sigm(float v) { return 1.f / (1.f + __expf(-v)); }

// ---- grid-wide sense-reversing barrier ----
__device__ __forceinline__ void gridbar() {
    __syncthreads();
    __threadfence();
    if (threadIdx.x == 0) {
        unsigned my = g_gen;
        unsigned a = atomicAdd(&g_count, 1u);
        if (a == NCTA - 1u) {
            g_count = 0;
            __threadfence();
            g_gen = my + 1u;
        } else {
            while (g_gen == my) { }
        }
    }
    __syncthreads();
    __threadfence();
}

// ---- stage one 128-k chunk (both bf16 planes) of 64 h rows via cp.async ----
__device__ __forceinline__ void stage_chunk(u32 dst, const us16* hi, const us16* lo,
                                            int B0, int kc, int tid) {
    #pragma unroll
    for (int i = 0; i < 8; i++) {
        int idx = tid + i * NTHR;          // 0..2047
        int pl  = idx >> 10;
        int rem = idx & 1023;
        int row = rem >> 4;                // 0..63
        int k16 = rem & 15;                // 16B units along k
        const us16* src = (pl ? lo : hi) + (size_t)(B0 + row) * EMB + kc + k16 * 8;
        cp16(dst + pl * HS_PL + row * APITCH + k16 * 16, src);
    }
    asm volatile("cp.async.commit_group;" ::: "memory");
}

// ---- full K=512 pass: acc[3][4] += split-bf16( src[64xK] ) @ ws^T ----
__device__ __forceinline__ void mma_pass(u32 smb, const us16* hi, const us16* lo, int B0,
                                         float acc[3][4], u32 a_off, u32 b4_off, u32 b2_off,
                                         int tid) {
    #pragma unroll
    for (int g = 0; g < 3; g++)
        #pragma unroll
        for (int q = 0; q < 4; q++) acc[g][q] = 0.f;

    stage_chunk(smb + HS_OFF, hi, lo, B0, 0, tid);
    for (int c = 0; c < 4; c++) {
        if (c < 3) {
            stage_chunk(smb + HS_OFF + ((c + 1) & 1) * HS_BUF, hi, lo, B0, (c + 1) * 128, tid);
            asm volatile("cp.async.wait_group 1;" ::: "memory");
        } else {
            asm volatile("cp.async.wait_group 0;" ::: "memory");
        }
        __syncthreads();

        u32 ab = smb + HS_OFF + (c & 1) * HS_BUF;
        #pragma unroll
        for (int kk = 0; kk < 8; kk++) {
            u32 ka = (u32)(kk * 32);
            u32 kb = (u32)(c * 256 + kk * 32);
            u32 ah0, ah1, ah2, ah3, al0, al1, al2, al3;
            u32 bh0, bh1, bh2, bh3, bg0, bg1;     // hi: gates 0,1 (x4) + gate 2 (x2)
            u32 cl0, cl1, cl2, cl3, cg0, cg1;     // lo planes
            ldsm_x4(ah0, ah1, ah2, ah3, ab + a_off + ka);
            ldsm_x4(al0, al1, al2, al3, ab + HS_PL + a_off + ka);
            ldsm_x4(bh0, bh1, bh2, bh3, smb + b4_off + kb);
            ldsm_x2(bg0, bg1,           smb + b2_off + kb);
            ldsm_x4(cl0, cl1, cl2, cl3, smb + WS_PL + b4_off + kb);
            ldsm_x2(cg0, cg1,           smb + WS_PL + b2_off + kb);
            // gate 0
            mma16816(acc[0], ah0, ah1, ah2, ah3, bh0, bh1);
            mma16816(acc[0], al0, al1, al2, al3, bh0, bh1);
            mma16816(acc[0], ah0, ah1, ah2, ah3, cl0, cl1);
            // gate 1
            mma16816(acc[1], ah0, ah1, ah2, ah3, bh2, bh3);
            mma16816(acc[1], al0, al1, al2, al3, bh2, bh3);
            mma16816(acc[1], ah0, ah1, ah2, ah3, cl2, cl3);
            // gate 2
            mma16816(acc[2], ah0, ah1, ah2, ah3, bg0, bg1);
            mma16816(acc[2], al0, al1, al2, al3, bg0, bg1);
            mma16816(acc[2], ah0, ah1, ah2, ah3, cg0, cg1);
        }
        __syncthreads();
    }
}

// ---- load a 48-row weight slice into bf16 hi/lo smem planes ----
__device__ __forceinline__ void load_ws(char* smraw, const float* wsrc, int J0, int tid) {
    us16* whi = (us16*)smraw;
    us16* wlo = (us16*)(smraw + WS_PL);
    for (int e = tid; e < 48 * EMB; e += NTHR) {
        int n = e >> 9, k = e & 511;
        int g = n >> 4, jj = n & 15;
        float w = wsrc[((size_t)(g * EMB + J0 + jj)) * EMB + k];
        __nv_bfloat16 h = __float2bfloat16(w);
        __nv_bfloat16 l = __float2bfloat16(w - __bfloat162float(h));
        whi[n * (BPITCH / 2) + k] = *(us16*)&h;
        wlo[n * (BPITCH / 2) + k] = *(us16*)&l;
    }
}

__global__ void __launch_bounds__(NTHR, 1)
gru_mma_kernel(const float* __restrict__ c,     const float* __restrict__ fc_w,
               const float* __restrict__ fc_b,  const float* __restrict__ w_ih,
               const float* __restrict__ b_ih,  const float* __restrict__ w_hh,
               const float* __restrict__ b_hh,  const float* __restrict__ head_w,
               const float* __restrict__ head_b,const int*   __restrict__ maxT,
               float* __restrict__ out)
{
    extern __shared__ char smraw[];
    const u32 smb = smem_u32(smraw);
    int* s_mx = (int*)(smraw + SMX_OFF);

    const int tid = threadIdx.x;
    const int cta = blockIdx.x;
    const int gt  = cta * NTHR + tid;
    const int wid = tid >> 5, lane = tid & 31;

    int T = (maxT != nullptr) ? maxT[0] : TMAX;
    if (T < 1 || T > TMAX) T = TMAX;

    const int B0 = (cta >> 5) * 64;          // 4 batch tiles of 64 rows
    const int J0 = (cta & 31) * 16;          // 32 j tiles of 16
    const int mtile = wid & 3, p = wid >> 2; // warp: m16 tile + 8-j group

    // ldmatrix per-lane byte offsets (step-invariant)
    const u32 a_off  = (u32)((mtile * 16 + (lane & 15)) * APITCH + (lane >> 4) * 16);
    const u32 b4_off = (u32)(((lane >> 4) * 16 + p * 8 + (lane & 7)) * BPITCH
                             + ((lane >> 3) & 1) * 16);
    const u32 b2_off = (u32)((32 + p * 8 + (lane & 7)) * BPITCH + ((lane >> 3) & 1) * 16);

    // this thread's 4 output cells: rows r0,r0+8 ; cols j0,j0+1
    const int r0 = B0 + mtile * 16 + (lane >> 2);
    const int j0 = J0 + p * 8 + 2 * (lane & 3);

    // ---------------- Phase A: init + x = tanh(c @ fc_w^T + fc_b) -> bf16 planes ---
    for (int i = gt; i < BATCH * EMB; i += NCTA * NTHR) {
        g_hp[0][0][i] = 0; g_hp[0][1][i] = 0;
    }
    for (int i = gt; i < TMAX; i += NCTA * NTHR) ((volatile int*)g_md)[i] = 0;

    for (int o = gt; o < BATCH * EMB; o += NCTA * NTHR) {
        int b = o >> 9, i = o & 511;
        const float4* cr = (const float4*)(c + (size_t)b * EMB);
        const float4* wr = (const float4*)(fc_w + (size_t)i * EMB);
        float s = 0.f;
        #pragma unroll 8
        for (int k = 0; k < EMB / 4; k++) {
            float4 a = cr[k], wv = wr[k];
            s += a.x * wv.x + a.y * wv.y + a.z * wv.z + a.w * wv.w;
        }
        float x = tanhf(s + fc_b[i]);
        __nv_bfloat16 xh = __float2bfloat16(x);
        __nv_bfloat16 xl = __float2bfloat16(x - __bfloat162float(xh));
        g_xp[0][o] = *(us16*)&xh; g_xp[1][o] = *(us16*)&xl;
    }
    gridbar();

    // ---------------- gi pass: ws <- w_ih ; acc = x @ w_ih^T ------------------------
    load_ws(smraw, w_ih, J0, tid);
    __syncthreads();

    float acc[3][4];
    mma_pass(smb, g_xp[0], g_xp[1], B0, acc, a_off, b4_off, b2_off, tid);

    float gir[4], giz[4], gin[4], bhn[4], hprev[4];
    #pragma unroll
    for (int q = 0; q < 4; q++) {
        int jq = j0 + (q & 1);
        gir[q] = acc[0][q] + b_ih[jq]           + b_hh[jq];
        giz[q] = acc[1][q] + b_ih[EMB + jq]     + b_hh[EMB + jq];
        gin[q] = acc[2][q] + b_ih[2 * EMB + jq];
        bhn[q] = b_hh[2 * EMB + jq];
        hprev[q] = 0.f;
    }
    __syncthreads();

    // ---------------- ws <- w_hh (resident for the whole recurrence) ---------------
    load_ws(smraw, w_hh, J0, tid);
    __syncthreads();

    const int group = tid >> 4, lane16 = tid & 15;

    // ---------------- Recurrent loop -----------------------------------------------
    for (int t = 0; t < T; t++) {
        if (tid == 0) *s_mx = 0;

        mma_pass(smb, g_hp[t & 1][0], g_hp[t & 1][1], B0, acc, a_off, b4_off, b2_off, tid);

        us16* nhi = g_hp[(t + 1) & 1][0];
        us16* nlo = g_hp[(t + 1) & 1][1];
        float mx = 0.f;
        u32 packh[2], packl[2];
        #pragma unroll
        for (int q = 0; q < 4; q++) {
            float r = sigm(gir[q] + acc[0][q]);
            float z = sigm(giz[q] + acc[1][q]);
            float n = tanhf(gin[q] + r * (acc[2][q] + bhn[q]));
            float hnew = (1.f - z) * n + z * hprev[q];
            mx = fmaxf(mx, fabsf(hnew - hprev[q]));
            hprev[q] = hnew;
            __nv_bfloat16 hh = __float2bfloat16(hnew);
            __nv_bfloat16 hl = __float2bfloat16(hnew - __bfloat162float(hh));
            int half = q >> 1, slot = q & 1;
            ((us16*)&packh[half])[slot] = *(us16*)&hh;
            ((us16*)&packl[half])[slot] = *(us16*)&hl;
        }
        size_t o0 = (size_t)r0 * EMB + j0, o1 = (size_t)(r0 + 8) * EMB + j0;
        __stcg((u32*)(nhi + o0), packh[0]);
        __stcg((u32*)(nhi + o1), packh[1]);
        __stcg((u32*)(nlo + o0), packl[0]);
        __stcg((u32*)(nlo + o1), packl[1]);

        atomicMax(s_mx, __float_as_int(mx));
        __syncthreads();
        if (tid == 0) atomicMax(&g_md[t], *s_mx);

        gridbar();   // h_{t+1} planes + g_md[t] globally visible

        bool conv = (__int_as_float(((volatile int*)g_md)[t]) < CONV_EPS);

        // head: out[:, t, :] = h_{t+1} @ head_w^T + head_b (1536 dots / 128 CTAs = 12)
        if (group < 12) {
            int pr = cta * 12 + group;
            int b = pr / NCLS, k = pr % NCLS;
            const us16* phi = nhi + (size_t)b * EMB;
            const us16* plo = nlo + (size_t)b * EMB;
            const float* wr = head_w + (size_t)k * EMB;
            float s = 0.f;
            #pragma unroll 8
            for (int jj = lane16; jj < EMB; jj += 16) {
                us16 uh = __ldcg(&phi[jj]), ul = __ldcg(&plo[jj]);
                float hv = __bfloat162float(*(__nv_bfloat16*)&uh)
                         + __bfloat162float(*(__nv_bfloat16*)&ul);
                s += hv * wr[jj];
            }
            unsigned m = 0xFFFFu << (tid & 16);
            s += __shfl_down_sync(m, s, 8, 16);
            s += __shfl_down_sync(m, s, 4, 16);
            s += __shfl_down_sync(m, s, 2, 16);
            s += __shfl_down_sync(m, s, 1, 16);
            if (lane16 == 0) {
                float val = s + head_b[k];
                size_t base = (size_t)b * T * NCLS + (size_t)k;
                out[base + (size_t)t * NCLS] = val;
                if (conv) {
                    for (int tt = t + 1; tt < T; tt++)
                        out[base + (size_t)tt * NCLS] = val;
                }
            }
        }
        if (conv) break;
    }
}

extern "C" void kernel_launch(void* const* d_in, const int* in_sizes, int n_in,
                              void* d_out, int out_size)
{
    (void)in_sizes; (void)out_size;
    const float* c      = (const float*)d_in[0];
    const float* fc_w   = (const float*)d_in[1];
    const float* fc_b   = (const float*)d_in[2];
    const float* w_ih   = (const float*)d_in[3];
    const float* b_ih   = (const float*)d_in[4];
    const float* w_hh   = (const float*)d_in[5];
    const float* b_hh   = (const float*)d_in[6];
    const float* head_w = (const float*)d_in[7];
    const float* head_b = (const float*)d_in[8];
    const int*   maxT   = (n_in > 9) ? (const int*)d_in[9] : nullptr;

    cudaFuncSetAttribute(gru_mma_kernel,
                         cudaFuncAttributeMaxDynamicSharedMemorySize, SMEM_BYTES);
    gru_mma_kernel<<<NCTA, NTHR, SMEM_BYTES>>>(c, fc_w, fc_b, w_ih, b_ih, w_hh, b_hh,
                                               head_w, head_b, maxT, (float*)d_out);
}

// round 8
// speedup vs baseline: 5.1693x; 1.2290x over previous
#include <cuda_runtime.h>
#include <cuda_fp16.h>

#define EMB   512
#define BATCH 256
#define NCLS  6
#define NCTA  128
#define NGRP  32          // CTAs per independent b-group
#define NTHR  256
#define TMAX  512
#define CONV_EPS 1.5e-3f

#define APITCH 272    // bytes/row of h chunk in smem
#define BPITCH 1040   // bytes/row of w in smem
#define WS_PL  49920  // one w plane: 48 * 1040
#define HS_OFF 99840
#define HS_PL  17408  // one h plane chunk: 64 * 272
#define HS_BUF 34816  // 2 planes
#define SMEM_BYTES (HS_OFF + 3 * HS_BUF)   // 204288

typedef unsigned int u32;
typedef unsigned long long u64;
typedef unsigned short us16;

// ---- persistent device state ----
__device__ us16 g_xp[2][BATCH * EMB];        // x fp16 hi/lo planes
__device__ us16 g_hp[2][2][BATCH * EMB];     // h[step parity][plane]
__device__ int  g_md4[4][TMAX];
__device__ unsigned g_cnt4[4 * 32];          // 128B-padded per group
__device__ volatile unsigned g_gen4[4 * 32];

__device__ __forceinline__ u32 smem_u32(const void* p) {
    u32 a; asm("{ .reg .u64 t; cvta.to.shared.u64 t, %1; cvt.u32.u64 %0, t; }" : "=r"(a) : "l"(p));
    return a;
}
__device__ __forceinline__ void cp16(u32 dst, const void* src) {
    u64 g = (u64)__cvta_generic_to_global(src);
    asm volatile("cp.async.cg.shared.global [%0], [%1], 16;" :: "r"(dst), "l"(g));
}
__device__ __forceinline__ void ldsm_x4(u32& r0, u32& r1, u32& r2, u32& r3, u32 addr) {
    asm volatile("ldmatrix.sync.aligned.m8n8.x4.shared.b16 {%0,%1,%2,%3}, [%4];"
                 : "=r"(r0), "=r"(r1), "=r"(r2), "=r"(r3) : "r"(addr));
}
__device__ __forceinline__ void ldsm_x2(u32& r0, u32& r1, u32 addr) {
    asm volatile("ldmatrix.sync.aligned.m8n8.x2.shared.b16 {%0,%1}, [%2];"
                 : "=r"(r0), "=r"(r1) : "r"(addr));
}
__device__ __forceinline__ void mma16816(float* d, u32 a0, u32 a1, u32 a2, u32 a3,
                                         u32 b0, u32 b1) {
    asm volatile("mma.sync.aligned.m16n8k16.row.col.f32.f16.f16.f32 "
                 "{%0,%1,%2,%3}, {%4,%5,%6,%7}, {%8,%9}, {%0,%1,%2,%3};"
                 : "+f"(d[0]), "+f"(d[1]), "+f"(d[2]), "+f"(d[3])
                 : "r"(a0), "r"(a1), "r"(a2), "r"(a3), "r"(b0), "r"(b1));
}
__device__ __forceinline__ float sigm(float v) { return 1.f / (1.f + __expf(-v)); }

// ---- per-group (32-CTA) sense-reversing barrier ----
__device__ __forceinline__ void groupbar(int bt) {
    __syncthreads();
    __threadfence();
    if (threadIdx.x == 0) {
        unsigned* cnt = &g_cnt4[bt * 32];
        volatile unsigned* gen = &g_gen4[bt * 32];
        unsigned my = *gen;
        unsigned a = atomicAdd(cnt, 1u);
        if (a == NGRP - 1u) {
            *cnt = 0;
            __threadfence();
            *gen = my + 1u;
        } else {
            while (*gen == my) { }
        }
    }
    __syncthreads();
    __threadfence();
}

// ---- stage one 128-k chunk (both fp16 planes) of 64 h rows via cp.async ----
__device__ __forceinline__ void stage_chunk(u32 dst, const us16* hi, const us16* lo,
                                            int B0, int kc, int tid) {
    #pragma unroll
    for (int i = 0; i < 8; i++) {
        int idx = tid + i * NTHR;          // 0..2047
        int pl  = idx >> 10;
        int rem = idx & 1023;
        int row = rem >> 4;                // 0..63
        int k16 = rem & 15;
        const us16* src = (pl ? lo : hi) + (size_t)(B0 + row) * EMB + kc + k16 * 8;
        cp16(dst + pl * HS_PL + row * APITCH + k16 * 16, src);
    }
    asm volatile("cp.async.commit_group;" ::: "memory");
}

// ---- full K=512 pass: acc[3][4] += split-fp16( src[64xK] ) @ ws^T ----
// 3 smem buffers, 1 syncthreads/chunk, prefetch distance 1.
__device__ __forceinline__ void mma_pass(u32 smb, const us16* hi, const us16* lo, int B0,
                                         float acc[3][4], u32 a_off, u32 b4_off, u32 b2_off,
                                         int tid) {
    #pragma unroll
    for (int g = 0; g < 3; g++)
        #pragma unroll
        for (int q = 0; q < 4; q++) acc[g][q] = 0.f;

    #pragma unroll 1
    for (int c = 0; c < 4; c++) {
        if (c < 3) {
            stage_chunk(smb + HS_OFF + ((c + 1) % 3) * HS_BUF, hi, lo, B0, (c + 1) * 128, tid);
            asm volatile("cp.async.wait_group 1;" ::: "memory");
        } else {
            asm volatile("cp.async.wait_group 0;" ::: "memory");
        }
        __syncthreads();

        u32 ab = smb + HS_OFF + (c % 3) * HS_BUF;
        #pragma unroll
        for (int kk = 0; kk < 8; kk++) {
            u32 ka = (u32)(kk * 32);
            u32 kb = (u32)(c * 256 + kk * 32);
            u32 ah0, ah1, ah2, ah3, al0, al1, al2, al3;
            u32 bh0, bh1, bh2, bh3, bg0, bg1;
            u32 cl0, cl1, cl2, cl3, cg0, cg1;
            ldsm_x4(ah0, ah1, ah2, ah3, ab + a_off + ka);
            ldsm_x4(al0, al1, al2, al3, ab + HS_PL + a_off + ka);
            ldsm_x4(bh0, bh1, bh2, bh3, smb + b4_off + kb);
            ldsm_x2(bg0, bg1,           smb + b2_off + kb);
            ldsm_x4(cl0, cl1, cl2, cl3, smb + WS_PL + b4_off + kb);
            ldsm_x2(cg0, cg1,           smb + WS_PL + b2_off + kb);
            mma16816(acc[0], ah0, ah1, ah2, ah3, bh0, bh1);
            mma16816(acc[0], al0, al1, al2, al3, bh0, bh1);
            mma16816(acc[0], ah0, ah1, ah2, ah3, cl0, cl1);
            mma16816(acc[1], ah0, ah1, ah2, ah3, bh2, bh3);
            mma16816(acc[1], al0, al1, al2, al3, bh2, bh3);
            mma16816(acc[1], ah0, ah1, ah2, ah3, cl2, cl3);
            mma16816(acc[2], ah0, ah1, ah2, ah3, bg0, bg1);
            mma16816(acc[2], al0, al1, al2, al3, bg0, bg1);
            mma16816(acc[2], ah0, ah1, ah2, ah3, cg0, cg1);
        }
    }
}

// ---- load a 48-row weight slice into fp16 hi/lo smem planes ----
__device__ __forceinline__ void load_ws(char* smraw, const float* wsrc, int J0, int tid) {
    us16* whi = (us16*)smraw;
    us16* wlo = (us16*)(smraw + WS_PL);
    for (int e = tid; e < 48 * EMB; e += NTHR) {
        int n = e >> 9, k = e & 511;
        int g = n >> 4, jj = n & 15;
        float w = wsrc[((size_t)(g * EMB + J0 + jj)) * EMB + k];
        __half h = __float2half_rn(w);
        __half l = __float2half_rn(w - __half2float(h));
        whi[n * (BPITCH / 2) + k] = *(us16*)&h;
        wlo[n * (BPITCH / 2) + k] = *(us16*)&l;
    }
}

__global__ void __launch_bounds__(NTHR, 1)
gru_mma_kernel(const float* __restrict__ c,     const float* __restrict__ fc_w,
               const float* __restrict__ fc_b,  const float* __restrict__ w_ih,
               const float* __restrict__ b_ih,  const float* __restrict__ w_hh,
               const float* __restrict__ b_hh,  const float* __restrict__ head_w,
               const float* __restrict__ head_b,const int*   __restrict__ maxT,
               float* __restrict__ out)
{
    extern __shared__ char smraw[];
    const u32 smb = smem_u32(smraw);
    __shared__ int s_mx;

    const int tid = threadIdx.x;
    const int cta = blockIdx.x;
    const int wid = tid >> 5, lane = tid & 31;

    int T = (maxT != nullptr) ? maxT[0] : TMAX;
    if (T < 1 || T > TMAX) T = TMAX;

    const int bt = cta >> 5;                 // b-group 0..3 (independent)
    const int jt = cta & 31;                 // j-tile within group
    const int B0 = bt * 64;
    const int J0 = jt * 16;
    const int lg = jt * NTHR + tid;          // 0..8191 within group
    const int mtile = wid & 3, p = wid >> 2;

    // ldmatrix per-lane byte offsets
    const u32 a_off  = (u32)((mtile * 16 + (lane & 15)) * APITCH + (lane >> 4) * 16);
    const u32 b4_off = (u32)(((lane >> 4) * 16 + p * 8 + (lane & 7)) * BPITCH
                             + ((lane >> 3) & 1) * 16);
    const u32 b2_off = (u32)((32 + p * 8 + (lane & 7)) * BPITCH + ((lane >> 3) & 1) * 16);

    // this thread's 4 output cells: rows r0,r0+8 ; cols j0,j0+1
    const int r0 = B0 + mtile * 16 + (lane >> 2);
    const int j0 = J0 + p * 8 + 2 * (lane & 3);

    const int group16 = tid >> 4, lane16 = tid & 15;
    // head assignment (group-local): 384 dots over 32 CTAs
    const int hp_idx = jt * 12 + group16;               // 0..383 (group16<12)
    const int hb = B0 + hp_idx / NCLS, hk = hp_idx % NCLS;

    // ---------------- Phase A (group-local): init + x = tanh(c @ fc_w^T + fc_b) ----
    for (int i = lg; i < 64 * EMB; i += NGRP * NTHR) {
        int o = B0 * EMB + i;
        g_hp[0][0][o] = 0; g_hp[0][1][o] = 0;
    }
    for (int i = lg; i < TMAX; i += NGRP * NTHR) ((volatile int*)g_md4[bt])[i] = 0;

    for (int i = lg; i < 64 * EMB; i += NGRP * NTHR) {
        int o = B0 * EMB + i;
        int b = o >> 9, ii = o & 511;
        const float4* cr = (const float4*)(c + (size_t)b * EMB);
        const float4* wr = (const float4*)(fc_w + (size_t)ii * EMB);
        float s = 0.f;
        #pragma unroll 8
        for (int k = 0; k < EMB / 4; k++) {
            float4 a = cr[k], wv = wr[k];
            s += a.x * wv.x + a.y * wv.y + a.z * wv.z + a.w * wv.w;
        }
        float x = tanhf(s + fc_b[ii]);
        __half xh = __float2half_rn(x);
        __half xl = __float2half_rn(x - __half2float(xh));
        g_xp[0][o] = *(us16*)&xh; g_xp[1][o] = *(us16*)&xl;
    }
    groupbar(bt);

    // ---------------- gi pass: ws <- w_ih ; acc = x @ w_ih^T -----------------------
    load_ws(smraw, w_ih, J0, tid);
    __syncthreads();

    float acc[3][4];
    stage_chunk(smb + HS_OFF, g_xp[0], g_xp[1], B0, 0, tid);
    mma_pass(smb, g_xp[0], g_xp[1], B0, acc, a_off, b4_off, b2_off, tid);

    float gir[4], giz[4], gin[4], bhn[4], hprev[4];
    #pragma unroll
    for (int q = 0; q < 4; q++) {
        int jq = j0 + (q & 1);
        gir[q] = acc[0][q] + b_ih[jq]           + b_hh[jq];
        giz[q] = acc[1][q] + b_ih[EMB + jq]     + b_hh[EMB + jq];
        gin[q] = acc[2][q] + b_ih[2 * EMB + jq];
        bhn[q] = b_hh[2 * EMB + jq];
        hprev[q] = 0.f;
    }
    __syncthreads();

    // ---------------- ws <- w_hh (resident for the whole recurrence) ---------------
    load_ws(smraw, w_hh, J0, tid);
    __syncthreads();

    const float* hw = head_w + (size_t)hk * EMB;
    const unsigned shm = 0xFFFFu << (tid & 16);

    // ---------------- Recurrent loop -----------------------------------------------
    for (int t = 0; t < T; t++) {
        const us16* chi = g_hp[t & 1][0];
        const us16* clo = g_hp[t & 1][1];
        us16* nhi = g_hp[(t + 1) & 1][0];
        us16* nlo = g_hp[(t + 1) & 1][1];

        if (tid == 0) s_mx = 0;
        // kick off chunk 0 of h_t staging, then do the deferred head(t-1) in its shadow
        stage_chunk(smb + HS_OFF, chi, clo, B0, 0, tid);

        if (t > 0 && group16 < 12) {
            // head for step t-1 reads h_t (= chi/clo) — same lines being staged
            const us16* phi = chi + (size_t)hb * EMB;
            const us16* plo = clo + (size_t)hb * EMB;
            float s = 0.f;
            #pragma unroll 8
            for (int jj = lane16; jj < EMB; jj += 16) {
                us16 uh = __ldcg(&phi[jj]), ul = __ldcg(&plo[jj]);
                s += (__half2float(*(__half*)&uh) + __half2float(*(__half*)&ul)) * hw[jj];
            }
            s += __shfl_down_sync(shm, s, 8, 16);
            s += __shfl_down_sync(shm, s, 4, 16);
            s += __shfl_down_sync(shm, s, 2, 16);
            s += __shfl_down_sync(shm, s, 1, 16);
            if (lane16 == 0)
                out[(size_t)hb * T * NCLS + (size_t)(t - 1) * NCLS + hk] = s + head_b[hk];
        }

        mma_pass(smb, chi, clo, B0, acc, a_off, b4_off, b2_off, tid);

        float mx = 0.f;
        u32 packh[2], packl[2];
        #pragma unroll
        for (int q = 0; q < 4; q++) {
            float r = sigm(gir[q] + acc[0][q]);
            float z = sigm(giz[q] + acc[1][q]);
            float n = tanhf(gin[q] + r * (acc[2][q] + bhn[q]));
            float hnew = (1.f - z) * n + z * hprev[q];
            mx = fmaxf(mx, fabsf(hnew - hprev[q]));
            hprev[q] = hnew;
            __half hh = __float2half_rn(hnew);
            __half hl = __float2half_rn(hnew - __half2float(hh));
            int half = q >> 1, slot = q & 1;
            ((us16*)&packh[half])[slot] = *(us16*)&hh;
            ((us16*)&packl[half])[slot] = *(us16*)&hl;
        }
        size_t o0 = (size_t)r0 * EMB + j0, o1 = (size_t)(r0 + 8) * EMB + j0;
        __stcg((u32*)(nhi + o0), packh[0]);
        __stcg((u32*)(nhi + o1), packh[1]);
        __stcg((u32*)(nlo + o0), packl[0]);
        __stcg((u32*)(nlo + o1), packl[1]);

        atomicMax(&s_mx, __float_as_int(mx));
        __syncthreads();
        if (tid == 0) atomicMax(&g_md4[bt][t], s_mx);

        groupbar(bt);   // h_{t+1} + conv flag visible within group

        bool conv = (__int_as_float(((volatile int*)g_md4[bt])[t]) < CONV_EPS);

        if (conv || t == T - 1) {
            // tail head for step t (+ fixed-point broadcast if converged)
            if (group16 < 12) {
                const us16* phi = nhi + (size_t)hb * EMB;
                const us16* plo = nlo + (size_t)hb * EMB;
                float s = 0.f;
                #pragma unroll 8
                for (int jj = lane16; jj < EMB; jj += 16) {
                    us16 uh = __ldcg(&phi[jj]), ul = __ldcg(&plo[jj]);
                    s += (__half2float(*(__half*)&uh) + __half2float(*(__half*)&ul)) * hw[jj];
                }
                s += __shfl_down_sync(shm, s, 8, 16);
                s += __shfl_down_sync(shm, s, 4, 16);
                s += __shfl_down_sync(shm, s, 2, 16);
                s += __shfl_down_sync(shm, s, 1, 16);
                if (lane16 == 0) {
                    float val = s + head_b[hk];
                    size_t base = (size_t)hb * T * NCLS + (size_t)hk;
                    out[base + (size_t)t * NCLS] = val;
                    for (int tt = t + 1; tt < T; tt++)
                        out[base + (size_t)tt * NCLS] = val;
                }
            }
            break;
        }
    }
}

extern "C" void kernel_launch(void* const* d_in, const int* in_sizes, int n_in,
                              void* d_out, int out_size)
{
    (void)in_sizes; (void)out_size;
    const float* c      = (const float*)d_in[0];
    const float* fc_w   = (const float*)d_in[1];
    const float* fc_b   = (const float*)d_in[2];
    const float* w_ih   = (const float*)d_in[3];
    const float* b_ih   = (const float*)d_in[4];
    const float* w_hh   = (const float*)d_in[5];
    const float* b_hh   = (const float*)d_in[6];
    const float* head_w = (const float*)d_in[7];
    const float* head_b = (const float*)d_in[8];
    const int*   maxT   = (n_in > 9) ? (const int*)d_in[9] : nullptr;

    cudaFuncSetAttribute(gru_mma_kernel,
                         cudaFuncAttributeMaxDynamicSharedMemorySize, SMEM_BYTES);
    gru_mma_kernel<<<NCTA, NTHR, SMEM_BYTES>>>(c, fc_w, fc_b, w_ih, b_ih, w_hh, b_hh,
                                               head_w, head_b, maxT, (float*)d_out);
}